// round 12
// baseline (speedup 1.0000x reference)
#include <cuda_runtime.h>
#include <cuda_fp16.h>

#define T_STEPS 200
#define NIN     5
#define H       32
#define G4      128
#define NB      16            // batches per warp
#define THREADS 32            // ONE warp per CTA

#define WPITCH  56                        // halfs per W row (112 B, LDSM conflict-free)
#define HPITCH  48                        // bytes per Hbuf row

struct SmemLayout {
    __half Whi[G4][WPITCH];               // 14336 B
    __half Hbuf[48][HPITCH / 2];          // 2304 B
};

// ---------- PTX helpers ----------
__device__ __forceinline__ unsigned smem_u32(const void* p) {
    unsigned a;
    asm("{ .reg .u64 t; cvta.to.shared.u64 t, %1; cvt.u32.u64 %0, t; }"
        : "=r"(a) : "l"(p));
    return a;
}
__device__ __forceinline__ void ldsm_x4(unsigned& a0, unsigned& a1,
                                        unsigned& a2, unsigned& a3, unsigned addr) {
    asm volatile("ldmatrix.sync.aligned.m8n8.x4.shared.b16 {%0,%1,%2,%3}, [%4];"
                 : "=r"(a0), "=r"(a1), "=r"(a2), "=r"(a3) : "r"(addr));
}
__device__ __forceinline__ void ldsm_x4t(unsigned& b0, unsigned& b1,
                                         unsigned& b2, unsigned& b3, unsigned addr) {
    asm volatile("ldmatrix.sync.aligned.m8n8.x4.trans.shared.b16 {%0,%1,%2,%3}, [%4];"
                 : "=r"(b0), "=r"(b1), "=r"(b2), "=r"(b3) : "r"(addr));
}
#define MMA(Cr, A0, A1, A2, A3, B0, B1)                                        \
    asm volatile("mma.sync.aligned.m16n8k16.row.col.f32.f16.f16.f32 "          \
                 "{%0,%1,%2,%3}, {%4,%5,%6,%7}, {%8,%9}, {%0,%1,%2,%3};"       \
                 : "+f"((Cr)[0]), "+f"((Cr)[1]), "+f"((Cr)[2]), "+f"((Cr)[3])  \
                 : "r"(A0), "r"(A1), "r"(A2), "r"(A3), "r"(B0), "r"(B1))

__device__ __forceinline__ void sts32(unsigned addr, unsigned v) {
    asm volatile("st.shared.b32 [%0], %1;" :: "r"(addr), "r"(v) : "memory");
}
__device__ __forceinline__ void sts16(unsigned addr, unsigned short v) {
    asm volatile("st.shared.b16 [%0], %1;" :: "r"(addr), "h"(v) : "memory");
}

// ---------- packed f16x2 helpers ----------
__device__ __forceinline__ __half2 tanh2(__half2 v) {
    unsigned u = *reinterpret_cast<unsigned*>(&v), r;
    asm("tanh.approx.f16x2 %0, %1;" : "=r"(r) : "r"(u));
    return *reinterpret_cast<__half2*>(&r);
}
__device__ __forceinline__ __half2 pack2h(float e0, float e1) {   // low=e0
    unsigned r;
    asm("cvt.rn.f16x2.f32 %0, %1, %2;" : "=r"(r) : "f"(e1), "f"(e0));
    return *reinterpret_cast<__half2*>(&r);
}
__device__ __forceinline__ unsigned h2bits(__half2 v) {
    return *reinterpret_cast<unsigned*>(&v);
}
__device__ __forceinline__ __half2 bits2h(unsigned u) {
    return *reinterpret_cast<__half2*>(&u);
}

__global__ void __launch_bounds__(THREADS)
lstm_w1_kernel(const float* __restrict__ x,
               const float* __restrict__ W_ih,
               const float* __restrict__ W_hh,
               const float* __restrict__ b_ih,
               const float* __restrict__ b_hh,
               const float* __restrict__ W_fc,
               const float* __restrict__ b_fc,
               float* __restrict__ out, int B) {
    __shared__ __align__(16) SmemLayout sm;

    const int lane = threadIdx.x;
    const int gl   = lane >> 2;
    const int tl   = lane & 3;

    // ============ init: W fp16 (x_lo duplicated cols) ============
    for (int g = lane; g < G4; g += THREADS) {
        for (int k = 0; k < WPITCH; ++k) {
            float v;
            if (k < H)            v = W_hh[g * H + k];
            else if (k < 37)      v = W_ih[g * NIN + (k - 32)];
            else if (k == 37)     v = b_ih[g] + b_hh[g];
            else if (k >= 38 && k < 43) v = W_ih[g * NIN + (k - 38)];
            else                  v = 0.0f;
            sm.Whi[g][k] = __float2half(v);
        }
    }
    {   // zero H buffer
        unsigned* hz = (unsigned*)&sm.Hbuf[0][0];
        for (int i = lane; i < (48 * HPITCH) / 4; i += THREADS) hz[i] = 0u;
    }
    __syncwarp();
    if (lane < NB) sm.Hbuf[37][lane] = __float2half(1.0f);   // ones row k=37
    __syncwarp();

    const int wb0 = blockIdx.x * NB;

    const unsigned sbase = smem_u32(&sm);
    const unsigned laneA = (unsigned)((lane & 15) * (WPITCH * 2) + (lane >> 4) * 16);
    const unsigned hwarp = sbase + (unsigned)(G4 * WPITCH * 2);
    const unsigned addrB = hwarp + (unsigned)((lane & 15) * HPITCH + (lane >> 4) * 16);

    // ---- pin W fragments in registers (step-invariant, 96 regs) ----
    unsigned wa[8][3][4];
#pragma unroll
    for (int mt = 0; mt < 8; ++mt)
#pragma unroll
        for (int kc = 0; kc < 3; ++kc)
            ldsm_x4(wa[mt][kc][0], wa[mt][kc][1], wa[mt][kc][2], wa[mt][kc][3],
                    sbase + laneA + (unsigned)(mt * (16 * WPITCH * 2) + kc * 32));

    const float* xr = x + (size_t)(wb0 + lane) * (T_STEPS * NIN);  // lane<16 valid

    float xv[NIN];
    if (lane < NB) {
#pragma unroll
        for (int d = 0; d < NIN; ++d) xv[d] = xr[d];
    }

    // state: c fp32 (16), h packed f16x2 (8): hidx = 4p + 2rr + nt (pair e0/e1)
    float creg[16];
    __half2 h2[8];
#pragma unroll
    for (int i = 0; i < 16; ++i) creg[i] = 0.0f;
#pragma unroll
    for (int i = 0; i < 8; ++i) h2[i] = bits2h(0u);

    const __half2 h05 = __float2half2_rn(0.5f);

#pragma unroll 1
    for (int t = 0; t < T_STEPS; ++t) {
        // ---- write h (f16x2 pairs) ----
#pragma unroll
        for (int p = 0; p < 2; ++p)
#pragma unroll
            for (int rr = 0; rr < 2; ++rr) {
                const int u = p * 16 + rr * 8 + gl;
#pragma unroll
                for (int nt = 0; nt < 2; ++nt)
                    sts32(hwarp + (unsigned)(u * HPITCH + (nt * 8 + 2 * tl) * 2),
                          h2bits(h2[4 * p + 2 * rr + nt]));
            }
        // ---- write x rows: hi at 32..36, lo at 38..42 ----
        if (lane < NB) {
#pragma unroll
            for (int d = 0; d < NIN; ++d) {
                __half xh = __float2half(xv[d]);
                __half xl = __float2half(xv[d] - __half2float(xh));
                sts16(hwarp + (unsigned)((32 + d) * HPITCH + lane * 2),
                      *reinterpret_cast<unsigned short*>(&xh));
                sts16(hwarp + (unsigned)((38 + d) * HPITCH + lane * 2),
                      *reinterpret_cast<unsigned short*>(&xl));
            }
        }
        __syncwarp();

        // ---- prefetch next x ----
        if (t + 1 < T_STEPS && lane < NB) {
#pragma unroll
            for (int d = 0; d < NIN; ++d) xv[d] = xr[(t + 1) * NIN + d];
        }

        // ---- single-pass MMA from pinned registers ----
        float Cacc[8][2][4];
#pragma unroll
        for (int m = 0; m < 8; ++m)
#pragma unroll
            for (int n = 0; n < 2; ++n)
#pragma unroll
                for (int e = 0; e < 4; ++e) Cacc[m][n][e] = 0.0f;

#pragma unroll
        for (int kc = 0; kc < 3; ++kc) {
            unsigned rb0, rb1, rb2, rb3;
            ldsm_x4t(rb0, rb1, rb2, rb3, addrB + (unsigned)(kc * 16 * HPITCH));
#pragma unroll
            for (int mt = 0; mt < 8; ++mt) {
                MMA(Cacc[mt][0], wa[mt][kc][0], wa[mt][kc][1],
                    wa[mt][kc][2], wa[mt][kc][3], rb0, rb1);
                MMA(Cacc[mt][1], wa[mt][kc][0], wa[mt][kc][1],
                    wa[mt][kc][2], wa[mt][kc][3], rb2, rb3);
            }
        }

        // ---- packed f16x2 activations + fp32 c update ----
#pragma unroll
        for (int p = 0; p < 2; ++p)
#pragma unroll
            for (int nt = 0; nt < 2; ++nt)
#pragma unroll
                for (int rr = 0; rr < 2; ++rr) {
                    const int j0 = rr * 2, j1 = rr * 2 + 1;
                    __half2 ci = pack2h(Cacc[p][nt][j0],     Cacc[p][nt][j1]);
                    __half2 cf = pack2h(Cacc[2 + p][nt][j0], Cacc[2 + p][nt][j1]);
                    __half2 cg = pack2h(Cacc[4 + p][nt][j0], Cacc[4 + p][nt][j1]);
                    __half2 co = pack2h(Cacc[6 + p][nt][j0], Cacc[6 + p][nt][j1]);
                    __half2 gi = __hfma2(tanh2(__hmul2(ci, h05)), h05, h05);
                    __half2 gf = __hfma2(tanh2(__hmul2(cf, h05)), h05, h05);
                    __half2 gg = tanh2(cg);
                    __half2 go = __hfma2(tanh2(__hmul2(co, h05)), h05, h05);
                    __half2 ig = __hmul2(gi, gg);
                    const int idx = 8 * p + 4 * rr + 2 * nt;
                    float c0 = fmaf(__low2float(gf),  creg[idx],     __low2float(ig));
                    float c1 = fmaf(__high2float(gf), creg[idx + 1], __high2float(ig));
                    creg[idx]     = c0;
                    creg[idx + 1] = c1;
                    __half2 tc = tanh2(pack2h(c0, c1));
                    h2[4 * p + 2 * rr + nt] = __hmul2(go, tc);
                }
    }

    // ============ final projection ============
    float acc[4][2];
#pragma unroll
    for (int q = 0; q < 4; ++q) { acc[q][0] = 0.0f; acc[q][1] = 0.0f; }
#pragma unroll
    for (int p = 0; p < 2; ++p)
#pragma unroll
        for (int rr = 0; rr < 2; ++rr) {
            const int u = p * 16 + rr * 8 + gl;
            const float w0 = W_fc[u], w1 = W_fc[H + u];
#pragma unroll
            for (int nt = 0; nt < 2; ++nt) {
                const __half2 hv = h2[4 * p + 2 * rr + nt];
                const float hv0 = __low2float(hv), hv1 = __high2float(hv);
                acc[nt * 2 + 0][0] = fmaf(hv0, w0, acc[nt * 2 + 0][0]);
                acc[nt * 2 + 0][1] = fmaf(hv0, w1, acc[nt * 2 + 0][1]);
                acc[nt * 2 + 1][0] = fmaf(hv1, w0, acc[nt * 2 + 1][0]);
                acc[nt * 2 + 1][1] = fmaf(hv1, w1, acc[nt * 2 + 1][1]);
            }
        }
#pragma unroll
    for (int off = 4; off <= 16; off <<= 1)
#pragma unroll
        for (int q = 0; q < 4; ++q) {
            acc[q][0] += __shfl_xor_sync(0xffffffffu, acc[q][0], off);
            acc[q][1] += __shfl_xor_sync(0xffffffffu, acc[q][1], off);
        }
    if (lane < 4) {
        const float f0 = b_fc[0], f1 = b_fc[1];
#pragma unroll
        for (int nt = 0; nt < 2; ++nt)
#pragma unroll
            for (int e = 0; e < 2; ++e) {
                const int col = nt * 8 + 2 * lane + e;
                out[(wb0 + col) * 2 + 0] = acc[nt * 2 + e][0] + f0;
                out[(wb0 + col) * 2 + 1] = acc[nt * 2 + e][1] + f1;
            }
    }
}

extern "C" void kernel_launch(void* const* d_in, const int* in_sizes, int n_in,
                              void* d_out, int out_size) {
    const float* x    = (const float*)d_in[0];
    const float* W_ih = (const float*)d_in[1];
    const float* W_hh = (const float*)d_in[2];
    const float* b_ih = (const float*)d_in[3];
    const float* b_hh = (const float*)d_in[4];
    const float* W_fc = (const float*)d_in[5];
    const float* b_fc = (const float*)d_in[6];
    float* out = (float*)d_out;

    int B = in_sizes[0] / (T_STEPS * NIN);
    int blocks = (B + NB - 1) / NB;            // 1024 one-warp CTAs
    lstm_w1_kernel<<<blocks, THREADS>>>(x, W_ih, W_hh, b_ih, b_hh,
                                        W_fc, b_fc, out, B);
}

// round 13
// speedup vs baseline: 1.9718x; 1.9718x over previous
#include <cuda_runtime.h>
#include <cuda_fp16.h>

#define T_STEPS 200
#define NIN     5
#define H       32
#define G4      128
#define NB      16            // batches per warp (2 n-tiles)
#define WARPS   7             // 7 warps -> one CTA per SM, 7 warps/SM exactly
#define THREADS (WARPS * 32)

#define WPITCH  56                        // halfs per W row (112 B, LDSM conflict-free)
#define WBYTES  (G4 * WPITCH * 2)         // 14336
#define OFF_H   WBYTES
#define HPITCH  48                        // bytes per Hbuf row
#define HWARPSZ (48 * HPITCH)             // 2304 per warp

struct SmemLayout {
    __half Whi[G4][WPITCH];
    __half Hbuf[WARPS][48][HPITCH / 2];
};

// ---------- PTX helpers ----------
__device__ __forceinline__ unsigned smem_u32(const void* p) {
    unsigned a;
    asm("{ .reg .u64 t; cvta.to.shared.u64 t, %1; cvt.u32.u64 %0, t; }"
        : "=r"(a) : "l"(p));
    return a;
}
__device__ __forceinline__ void ldsm_x4(unsigned& a0, unsigned& a1,
                                        unsigned& a2, unsigned& a3, unsigned addr) {
    asm volatile("ldmatrix.sync.aligned.m8n8.x4.shared.b16 {%0,%1,%2,%3}, [%4];"
                 : "=r"(a0), "=r"(a1), "=r"(a2), "=r"(a3) : "r"(addr));
}
__device__ __forceinline__ void ldsm_x4t(unsigned& b0, unsigned& b1,
                                         unsigned& b2, unsigned& b3, unsigned addr) {
    asm volatile("ldmatrix.sync.aligned.m8n8.x4.trans.shared.b16 {%0,%1,%2,%3}, [%4];"
                 : "=r"(b0), "=r"(b1), "=r"(b2), "=r"(b3) : "r"(addr));
}
#define MMA(Cr, A0, A1, A2, A3, B0, B1)                                        \
    asm volatile("mma.sync.aligned.m16n8k16.row.col.f32.f16.f16.f32 "          \
                 "{%0,%1,%2,%3}, {%4,%5,%6,%7}, {%8,%9}, {%0,%1,%2,%3};"       \
                 : "+f"((Cr)[0]), "+f"((Cr)[1]), "+f"((Cr)[2]), "+f"((Cr)[3])  \
                 : "r"(A0), "r"(A1), "r"(A2), "r"(A3), "r"(B0), "r"(B1))

__device__ __forceinline__ void sts32(unsigned addr, unsigned v) {
    asm volatile("st.shared.b32 [%0], %1;" :: "r"(addr), "r"(v) : "memory");
}
__device__ __forceinline__ void sts16(unsigned addr, unsigned short v) {
    asm volatile("st.shared.b16 [%0], %1;" :: "r"(addr), "h"(v) : "memory");
}

// ---------- packed f16x2 helpers ----------
__device__ __forceinline__ __half2 tanh2(__half2 v) {
    unsigned u = *reinterpret_cast<unsigned*>(&v), r;
    asm("tanh.approx.f16x2 %0, %1;" : "=r"(r) : "r"(u));
    return *reinterpret_cast<__half2*>(&r);
}
__device__ __forceinline__ __half2 pack2h(float e0, float e1) {   // low=e0
    unsigned r;
    asm("cvt.rn.f16x2.f32 %0, %1, %2;" : "=r"(r) : "f"(e1), "f"(e0));
    return *reinterpret_cast<__half2*>(&r);
}
__device__ __forceinline__ unsigned h2bits(__half2 v) {
    return *reinterpret_cast<unsigned*>(&v);
}
__device__ __forceinline__ __half2 bits2h(unsigned u) {
    return *reinterpret_cast<__half2*>(&u);
}

__global__ void __launch_bounds__(THREADS, 1)
lstm_w7_kernel(const float* __restrict__ x,
               const float* __restrict__ W_ih,
               const float* __restrict__ W_hh,
               const float* __restrict__ b_ih,
               const float* __restrict__ b_hh,
               const float* __restrict__ W_fc,
               const float* __restrict__ b_fc,
               float* __restrict__ out, int B) {
    __shared__ __align__(16) SmemLayout sm;

    const int tid  = threadIdx.x;
    const int wid  = tid >> 5;
    const int lane = tid & 31;

    // ============ init: W fp16 (x_lo duplicated cols) ============
    for (int g = tid; g < G4; g += THREADS) {
        for (int k = 0; k < WPITCH; ++k) {
            float v;
            if (k < H)            v = W_hh[g * H + k];
            else if (k < 37)      v = W_ih[g * NIN + (k - 32)];
            else if (k == 37)     v = b_ih[g] + b_hh[g];
            else if (k >= 38 && k < 43) v = W_ih[g * NIN + (k - 38)];
            else                  v = 0.0f;
            sm.Whi[g][k] = __float2half(v);
        }
    }
    {   // zero H buffers
        unsigned* hz = (unsigned*)&sm.Hbuf[0][0][0];
        for (int i = tid; i < (WARPS * HWARPSZ) / 4; i += THREADS) hz[i] = 0u;
    }
    __syncthreads();
    if (tid < WARPS * NB)
        sm.Hbuf[tid / NB][37][tid % NB] = __float2half(1.0f);
    __syncthreads();

    const int wb0 = blockIdx.x * (WARPS * NB) + wid * NB;
    if (wb0 >= B) return;   // whole idle warps only; no CTA syncs below

    const unsigned sbase = smem_u32(&sm);
    const unsigned laneA = (unsigned)((lane & 15) * (WPITCH * 2) + (lane >> 4) * 16);
    const unsigned hwarp = sbase + OFF_H + wid * HWARPSZ;
    const unsigned addrB = hwarp + (unsigned)((lane & 15) * HPITCH + (lane >> 4) * 16);
    const int gl = lane >> 2;
    const int tl = lane & 3;

    // ---- pin W fragments in registers (step-invariant) ----
    unsigned wa[8][3][4];
#pragma unroll
    for (int mt = 0; mt < 8; ++mt)
#pragma unroll
        for (int kc = 0; kc < 3; ++kc)
            ldsm_x4(wa[mt][kc][0], wa[mt][kc][1], wa[mt][kc][2], wa[mt][kc][3],
                    sbase + laneA + (unsigned)(mt * (16 * WPITCH * 2) + kc * 32));

    const float* xr = x + (size_t)(wb0 + lane) * (T_STEPS * NIN);  // lane<16 valid

    float xv[NIN];
    if (lane < NB) {
#pragma unroll
        for (int d = 0; d < NIN; ++d) xv[d] = xr[d];
    }

    // state: c fp32 (16), h packed f16x2 (8): hidx = 4p + 2rr + nt (pair e0/e1)
    float creg[16];
    __half2 h2[8];
#pragma unroll
    for (int i = 0; i < 16; ++i) creg[i] = 0.0f;
#pragma unroll
    for (int i = 0; i < 8; ++i) h2[i] = bits2h(0u);

    const __half2 h05 = __float2half2_rn(0.5f);

#pragma unroll 1
    for (int t = 0; t < T_STEPS; ++t) {
        // ---- write h (f16x2 pairs) ----
#pragma unroll
        for (int p = 0; p < 2; ++p)
#pragma unroll
            for (int rr = 0; rr < 2; ++rr) {
                const int u = p * 16 + rr * 8 + gl;
#pragma unroll
                for (int nt = 0; nt < 2; ++nt)
                    sts32(hwarp + (unsigned)(u * HPITCH + (nt * 8 + 2 * tl) * 2),
                          h2bits(h2[4 * p + 2 * rr + nt]));
            }
        // ---- write x rows: hi at 32..36, lo at 38..42 ----
        if (lane < NB) {
#pragma unroll
            for (int d = 0; d < NIN; ++d) {
                __half xh = __float2half(xv[d]);
                __half xl = __float2half(xv[d] - __half2float(xh));
                sts16(hwarp + (unsigned)((32 + d) * HPITCH + lane * 2),
                      *reinterpret_cast<unsigned short*>(&xh));
                sts16(hwarp + (unsigned)((38 + d) * HPITCH + lane * 2),
                      *reinterpret_cast<unsigned short*>(&xl));
            }
        }
        __syncwarp();

        // ---- prefetch next x ----
        if (t + 1 < T_STEPS && lane < NB) {
#pragma unroll
            for (int d = 0; d < NIN; ++d) xv[d] = xr[(t + 1) * NIN + d];
        }

        // ---- single-pass MMA from pinned registers ----
        float Cacc[8][2][4];
#pragma unroll
        for (int m = 0; m < 8; ++m)
#pragma unroll
            for (int n = 0; n < 2; ++n)
#pragma unroll
                for (int e = 0; e < 4; ++e) Cacc[m][n][e] = 0.0f;

#pragma unroll
        for (int kc = 0; kc < 3; ++kc) {
            unsigned rb0, rb1, rb2, rb3;
            ldsm_x4t(rb0, rb1, rb2, rb3, addrB + (unsigned)(kc * 16 * HPITCH));
#pragma unroll
            for (int mt = 0; mt < 8; ++mt) {
                MMA(Cacc[mt][0], wa[mt][kc][0], wa[mt][kc][1],
                    wa[mt][kc][2], wa[mt][kc][3], rb0, rb1);
                MMA(Cacc[mt][1], wa[mt][kc][0], wa[mt][kc][1],
                    wa[mt][kc][2], wa[mt][kc][3], rb2, rb3);
            }
        }

        // ---- packed f16x2 activations + fp32 c update ----
#pragma unroll
        for (int p = 0; p < 2; ++p)
#pragma unroll
            for (int nt = 0; nt < 2; ++nt)
#pragma unroll
                for (int rr = 0; rr < 2; ++rr) {
                    const int j0 = rr * 2, j1 = rr * 2 + 1;
                    __half2 ci = pack2h(Cacc[p][nt][j0],     Cacc[p][nt][j1]);
                    __half2 cf = pack2h(Cacc[2 + p][nt][j0], Cacc[2 + p][nt][j1]);
                    __half2 cg = pack2h(Cacc[4 + p][nt][j0], Cacc[4 + p][nt][j1]);
                    __half2 co = pack2h(Cacc[6 + p][nt][j0], Cacc[6 + p][nt][j1]);
                    __half2 gi = __hfma2(tanh2(__hmul2(ci, h05)), h05, h05);
                    __half2 gf = __hfma2(tanh2(__hmul2(cf, h05)), h05, h05);
                    __half2 gg = tanh2(cg);
                    __half2 go = __hfma2(tanh2(__hmul2(co, h05)), h05, h05);
                    __half2 ig = __hmul2(gi, gg);
                    const int idx = 8 * p + 4 * rr + 2 * nt;
                    float c0 = fmaf(__low2float(gf),  creg[idx],     __low2float(ig));
                    float c1 = fmaf(__high2float(gf), creg[idx + 1], __high2float(ig));
                    creg[idx]     = c0;
                    creg[idx + 1] = c1;
                    __half2 tc = tanh2(pack2h(c0, c1));
                    h2[4 * p + 2 * rr + nt] = __hmul2(go, tc);
                }
    }

    // ============ final projection ============
    float acc[4][2];
#pragma unroll
    for (int q = 0; q < 4; ++q) { acc[q][0] = 0.0f; acc[q][1] = 0.0f; }
#pragma unroll
    for (int p = 0; p < 2; ++p)
#pragma unroll
        for (int rr = 0; rr < 2; ++rr) {
            const int u = p * 16 + rr * 8 + gl;
            const float w0 = W_fc[u], w1 = W_fc[H + u];
#pragma unroll
            for (int nt = 0; nt < 2; ++nt) {
                const __half2 hv = h2[4 * p + 2 * rr + nt];
                const float hv0 = __low2float(hv), hv1 = __high2float(hv);
                acc[nt * 2 + 0][0] = fmaf(hv0, w0, acc[nt * 2 + 0][0]);
                acc[nt * 2 + 0][1] = fmaf(hv0, w1, acc[nt * 2 + 0][1]);
                acc[nt * 2 + 1][0] = fmaf(hv1, w0, acc[nt * 2 + 1][0]);
                acc[nt * 2 + 1][1] = fmaf(hv1, w1, acc[nt * 2 + 1][1]);
            }
        }
#pragma unroll
    for (int off = 4; off <= 16; off <<= 1)
#pragma unroll
        for (int q = 0; q < 4; ++q) {
            acc[q][0] += __shfl_xor_sync(0xffffffffu, acc[q][0], off);
            acc[q][1] += __shfl_xor_sync(0xffffffffu, acc[q][1], off);
        }
    if (lane < 4) {
        const float f0 = b_fc[0], f1 = b_fc[1];
#pragma unroll
        for (int nt = 0; nt < 2; ++nt)
#pragma unroll
            for (int e = 0; e < 2; ++e) {
                const int col = nt * 8 + 2 * lane + e;
                out[(wb0 + col) * 2 + 0] = acc[nt * 2 + e][0] + f0;
                out[(wb0 + col) * 2 + 1] = acc[nt * 2 + e][1] + f1;
            }
    }
}

extern "C" void kernel_launch(void* const* d_in, const int* in_sizes, int n_in,
                              void* d_out, int out_size) {
    const float* x    = (const float*)d_in[0];
    const float* W_ih = (const float*)d_in[1];
    const float* W_hh = (const float*)d_in[2];
    const float* b_ih = (const float*)d_in[3];
    const float* b_hh = (const float*)d_in[4];
    const float* W_fc = (const float*)d_in[5];
    const float* b_fc = (const float*)d_in[6];
    float* out = (float*)d_out;

    int B = in_sizes[0] / (T_STEPS * NIN);
    int bpc = WARPS * NB;                      // 112 batches per CTA
    int blocks = (B + bpc - 1) / bpc;          // 147 CTAs -> ~1 per SM
    lstm_w7_kernel<<<blocks, THREADS>>>(x, W_ih, W_hh, b_ih, b_hh,
                                        W_fc, b_fc, out, B);
}